// round 2
// baseline (speedup 1.0000x reference)
#include <cuda_runtime.h>

// PCEN: smooth[t] = 0.975*smooth[t-1] + 0.025*x[t], smooth[0]=x[0]
//       out = (x * (smooth+1e-6)^-0.98 + 2)^0.5 - 2^0.5
//
// Parallelization: the EMA has decay 0.975; 0.975^512 = 2.4e-6, so each
// 512-sample chunk reconstructs its starting state from a 512-sample
// lookback (init = x[lookstart], then run the recurrence). Error in smooth
// is <= 0.975^512 * O(1) -> ~1e-5 relative in the output, far under 1e-3.

namespace {

constexpr int T_LEN = 4096;
constexpr int CHUNK = 512;
constexpr int LOOK  = 512;
constexpr int CPR   = T_LEN / CHUNK;  // 8 chunks per row

__device__ __forceinline__ float pcen_pt(float xv, float sm) {
    // x * (sm+eps)^-0.98 + 2, then sqrt, minus sqrt(2)
    float l = __log2f(sm + 1e-6f);          // MUFU.LG2
    float g = exp2f(-0.98f * l);            // MUFU.EX2
    float v = fmaf(xv, g, 2.0f);
    return rsqrtf(v) * v - 1.41421356237309515f;  // MUFU.RSQ; v >= 2 so safe
}

__global__ __launch_bounds__(128, 1)
void pcen_kernel(const float* __restrict__ x, float* __restrict__ out, int nrows) {
    constexpr float S = 0.025f, OMS = 0.975f;
    int tid = blockIdx.x * blockDim.x + threadIdx.x;
    // chunk in the slow dimension: whole warps share one chunk index
    // (no divergence between the chunk-0 path and the lookback path),
    // consecutive lanes hit consecutive rows.
    int row   = tid % nrows;
    int chunk = tid / nrows;
    if (chunk >= CPR) return;

    const float4* __restrict__ xr =
        reinterpret_cast<const float4*>(x) + (size_t)row * (T_LEN / 4);
    float4* __restrict__ orow =
        reinterpret_cast<float4*>(out) + (size_t)row * (T_LEN / 4);

    const int s4 = chunk * (CHUNK / 4);
    const int e4 = s4 + (CHUNK / 4);

    float sm;
    int i0;
    if (chunk == 0) {
        // exact start: smooth[0] = x[0]
        float4 v = xr[0];
        float4 o;
        sm = v.x;                     o.x = pcen_pt(v.x, sm);
        sm = fmaf(OMS, sm, S * v.y);  o.y = pcen_pt(v.y, sm);
        sm = fmaf(OMS, sm, S * v.z);  o.z = pcen_pt(v.z, sm);
        sm = fmaf(OMS, sm, S * v.w);  o.w = pcen_pt(v.w, sm);
        orow[0] = o;
        i0 = 1;
    } else {
        // warmup over the lookback window (FMA-only, no output)
        int w4 = s4 - LOOK / 4;
        float4 v = xr[w4];
        sm = v.x;
        sm = fmaf(OMS, sm, S * v.y);
        sm = fmaf(OMS, sm, S * v.z);
        sm = fmaf(OMS, sm, S * v.w);
        #pragma unroll 4
        for (int i = w4 + 1; i < s4; ++i) {
            v = xr[i];
            sm = fmaf(OMS, sm, S * v.x);
            sm = fmaf(OMS, sm, S * v.y);
            sm = fmaf(OMS, sm, S * v.z);
            sm = fmaf(OMS, sm, S * v.w);
        }
        i0 = s4;
    }

    #pragma unroll 4
    for (int i = i0; i < e4; ++i) {
        float4 v = xr[i];
        float4 o;
        sm = fmaf(OMS, sm, S * v.x);  o.x = pcen_pt(v.x, sm);
        sm = fmaf(OMS, sm, S * v.y);  o.y = pcen_pt(v.y, sm);
        sm = fmaf(OMS, sm, S * v.z);  o.z = pcen_pt(v.z, sm);
        sm = fmaf(OMS, sm, S * v.w);  o.w = pcen_pt(v.w, sm);
        orow[i] = o;
    }
}

}  // namespace

extern "C" void kernel_launch(void* const* d_in, const int* in_sizes, int n_in,
                              void* d_out, int out_size) {
    const float* x = (const float*)d_in[0];
    float* out = (float*)d_out;
    int nrows = in_sizes[0] / T_LEN;     // 64*128 = 8192 rows
    int total = nrows * CPR;             // 65536 threads
    int block = 128;
    int grid = (total + block - 1) / block;
    pcen_kernel<<<grid, block>>>(x, out, nrows);
}

// round 3
// speedup vs baseline: 1.6661x; 1.6661x over previous
#include <cuda_runtime.h>

// PCEN: smooth[t] = 0.975*smooth[t-1] + 0.025*x[t], smooth[0]=x[0]
//       out = (x * (smooth+1e-6)^-0.98 + 2)^0.5 - 2^0.5
//
// Chunked-scan with lookback (0.975^384 = 6e-5 -> ~1e-5 output error).
// Block = 128 threads = 128 rows at one chunk. Tiles of 32 floats/row are
// staged into SMEM via cp.async with fully coalesced global access
// (4 cache lines / 512B per warp instruction instead of 32 lines), the
// serial per-row EMA reads from SMEM, results are written back in place
// and stored to GMEM cooperatively (coalesced).

namespace {

constexpr int T_LEN = 4096;
constexpr int CHUNK = 512;
constexpr int LOOK  = 384;
constexpr int CPR   = T_LEN / CHUNK;   // 8 chunks per row
constexpr int RPB   = 128;             // rows per block == threads per block
constexpr int TILE  = 32;              // floats per tile per row
constexpr int TF4   = TILE / 4;        // 8 float4 per row-tile
constexpr int PAD   = 9;               // smem row stride in float4 (padded)

__device__ __forceinline__ float pcen_pt(float xv, float sm) {
    float l = __log2f(sm + 1e-6f);                // MUFU.LG2
    float g = exp2f(-0.98f * l);                  // MUFU.EX2
    float v = fmaf(xv, g, 2.0f);
    return rsqrtf(v) * v - 1.41421356237309515f;  // MUFU.RSQ; v >= 2
}

__global__ __launch_bounds__(RPB, 6)
void pcen_kernel(const float* __restrict__ x, float* __restrict__ out,
                 int ngroups) {
    __shared__ float4 buf[2][RPB * PAD];

    const int tid      = threadIdx.x;
    const int rowgroup = blockIdx.x % ngroups;
    const int chunk    = blockIdx.x / ngroups;
    const int row0     = rowgroup * RPB;

    const int cs = chunk * CHUNK;
    const int ws = max(0, cs - LOOK);                 // window start (mult of 32)
    const int n_tiles  = (cs + CHUNK - ws) / TILE;    // 16 (chunk 0) or 28
    const int out_from = (cs - ws) / TILE;            // 0 or 12

    const float* xbase = x + (size_t)row0 * T_LEN + ws;
    float4* obase = reinterpret_cast<float4*>(out) +
                    (size_t)row0 * (T_LEN / 4) + cs / 4;

    // cooperative copy mapping: copy c = i*128 + tid -> r = c/8, f = c%8
    // lanes 0..7 cover 32 consecutive floats of one row -> coalesced.
    const int cr = tid >> 3;   // 0..15
    const int cf = tid & 7;

    auto issue_tile = [&](int k, int b) {
        const float* g0 = xbase + k * TILE;
        #pragma unroll
        for (int i = 0; i < 8; ++i) {
            int r = cr + i * 16;
            const float* g = g0 + r * T_LEN + cf * 4;
            unsigned s = (unsigned)__cvta_generic_to_shared(&buf[b][r * PAD + cf]);
            asm volatile("cp.async.cg.shared.global [%0], [%1], 16;\n"
                         :: "r"(s), "l"(g));
        }
        asm volatile("cp.async.commit_group;\n");
    };

    issue_tile(0, 0);

    float sm = 0.0f;
    constexpr float S = 0.025f, OMS = 0.975f;

    for (int k = 0; k < n_tiles; ++k) {
        if (k + 1 < n_tiles) {
            issue_tile(k + 1, (k + 1) & 1);
            asm volatile("cp.async.wait_group 1;\n");
        } else {
            asm volatile("cp.async.wait_group 0;\n");
        }
        __syncthreads();

        float4* myrow = &buf[k & 1][tid * PAD];
        const bool emit = (k >= out_from);

        #pragma unroll
        for (int f = 0; f < TF4; ++f) {
            float4 v = myrow[f];
            if (k == 0 && f == 0) sm = v.x;                 // exact/approx init
            else                  sm = fmaf(OMS, sm, S * v.x);
            float s0 = sm;
            sm = fmaf(OMS, sm, S * v.y);  float s1 = sm;
            sm = fmaf(OMS, sm, S * v.z);  float s2 = sm;
            sm = fmaf(OMS, sm, S * v.w);  float s3 = sm;
            if (emit) {
                float4 o;
                o.x = pcen_pt(v.x, s0);
                o.y = pcen_pt(v.y, s1);
                o.z = pcen_pt(v.z, s2);
                o.w = pcen_pt(v.w, s3);
                myrow[f] = o;                               // in-place
            }
        }

        if (emit) {
            __syncthreads();
            const int ko = k - out_from;
            #pragma unroll
            for (int i = 0; i < 8; ++i) {
                int r = cr + i * 16;
                obase[(size_t)r * (T_LEN / 4) + ko * TF4 + cf] =
                    buf[k & 1][r * PAD + cf];
            }
        }
        __syncthreads();   // buf[k&1] is refilled at iteration k+1
    }
}

}  // namespace

extern "C" void kernel_launch(void* const* d_in, const int* in_sizes, int n_in,
                              void* d_out, int out_size) {
    const float* x = (const float*)d_in[0];
    float* out = (float*)d_out;
    int nrows = in_sizes[0] / T_LEN;        // 8192
    int ngroups = nrows / RPB;              // 64
    int grid = ngroups * CPR;               // 512 blocks
    pcen_kernel<<<grid, RPB>>>(x, out, ngroups);
}

// round 4
// speedup vs baseline: 1.7694x; 1.0620x over previous
#include <cuda_runtime.h>

// PCEN: smooth[t] = 0.975*smooth[t-1] + 0.025*x[t], smooth[0]=x[0]
//       out = (x * (smooth+1e-6)^-0.98 + 2)^0.5 - 2^0.5
//
// Chunked scan with lookback (0.975^288 = 6.8e-4 -> ~6e-5 output error).
// 64-thread blocks = 64 rows x 1 chunk => grid 1024 (whole grid resident in
// one wave; chunk c+1's lookback hits chunk c's body in L2). 3-stage
// cp.async pipeline stages 64x32 tiles into SMEM with coalesced loads;
// the serial per-row EMA runs on padded (conflict-free) SMEM rows; output
// is written back in place and stored cooperatively (coalesced).

namespace {

constexpr int T_LEN  = 4096;
constexpr int CHUNK  = 512;
constexpr int LOOK   = 288;
constexpr int CPR    = T_LEN / CHUNK;   // 8
constexpr int RPB    = 64;              // rows per block == threads
constexpr int TILE   = 32;              // floats per tile per row
constexpr int TF4    = TILE / 4;        // 8
constexpr int PAD    = 9;               // smem row stride in float4
constexpr int STAGES = 3;

__device__ __forceinline__ float pcen_pt(float xv, float sm) {
    float l = __log2f(sm + 1e-6f);                // MUFU.LG2
    float g = exp2f(-0.98f * l);                  // MUFU.EX2
    float v = fmaf(xv, g, 2.0f);
    return rsqrtf(v) * v - 1.41421356237309515f;  // MUFU.RSQ; v >= 2
}

__global__ __launch_bounds__(RPB, 8)
void pcen_kernel(const float* __restrict__ x, float* __restrict__ out,
                 int ngroups) {
    __shared__ float4 buf[STAGES][RPB * PAD];

    const int tid      = threadIdx.x;
    const int rowgroup = blockIdx.x % ngroups;
    const int chunk    = blockIdx.x / ngroups;
    const int row0     = rowgroup * RPB;

    const int cs = chunk * CHUNK;
    const int ws = max(0, cs - LOOK);               // window start (mult of 32)
    const int n_tiles  = (cs + CHUNK - ws) / TILE;  // 16 (chunk 0) or 25
    const int out_from = (cs - ws) / TILE;          // 0 or 9

    const float* xbase = x + (size_t)row0 * T_LEN + ws;
    float4* obase = reinterpret_cast<float4*>(out) +
                    (size_t)row0 * (T_LEN / 4) + cs / 4;

    // cooperative copy: lanes 0..7 cover 32 consecutive floats of one row.
    const int cr = tid >> 3;   // 0..7
    const int cf = tid & 7;

    auto issue_tile = [&](int k) {
        if (k < n_tiles) {
            const float* g0 = xbase + k * TILE;
            float4* b = buf[k % STAGES];
            #pragma unroll
            for (int i = 0; i < 8; ++i) {
                int r = cr + i * 8;
                const float* g = g0 + (size_t)r * T_LEN + cf * 4;
                unsigned s = (unsigned)__cvta_generic_to_shared(&b[r * PAD + cf]);
                asm volatile("cp.async.cg.shared.global [%0], [%1], 16;\n"
                             :: "r"(s), "l"(g));
            }
        }
        asm volatile("cp.async.commit_group;\n");
    };

    issue_tile(0);
    issue_tile(1);

    float sm = 0.0f;
    constexpr float S = 0.025f, OMS = 0.975f;

    for (int k = 0; k < n_tiles; ++k) {
        issue_tile(k + 2);
        asm volatile("cp.async.wait_group 2;\n");
        __syncthreads();

        float4* myrow = &buf[k % STAGES][tid * PAD];
        const bool emit = (k >= out_from);

        #pragma unroll
        for (int f = 0; f < TF4; ++f) {
            float4 v = myrow[f];
            if (k == 0 && f == 0) sm = v.x;          // exact init
            else                  sm = fmaf(OMS, sm, S * v.x);
            float s0 = sm;
            sm = fmaf(OMS, sm, S * v.y);  float s1 = sm;
            sm = fmaf(OMS, sm, S * v.z);  float s2 = sm;
            sm = fmaf(OMS, sm, S * v.w);  float s3 = sm;
            if (emit) {
                float4 o;
                o.x = pcen_pt(v.x, s0);
                o.y = pcen_pt(v.y, s1);
                o.z = pcen_pt(v.z, s2);
                o.w = pcen_pt(v.w, s3);
                myrow[f] = o;                        // in-place
            }
        }

        if (emit) {
            __syncthreads();
            const int ko = k - out_from;
            const float4* b = buf[k % STAGES];
            #pragma unroll
            for (int i = 0; i < 8; ++i) {
                int r = cr + i * 8;
                obase[(size_t)r * (T_LEN / 4) + ko * TF4 + cf] =
                    b[r * PAD + cf];
            }
        }
        __syncthreads();   // buf[k%STAGES] is rewritten by issue at iter k+1
    }
}

}  // namespace

extern "C" void kernel_launch(void* const* d_in, const int* in_sizes, int n_in,
                              void* d_out, int out_size) {
    const float* x = (const float*)d_in[0];
    float* out = (float*)d_out;
    int nrows = in_sizes[0] / T_LEN;        // 8192
    int ngroups = nrows / RPB;              // 128
    int grid = ngroups * CPR;               // 1024 blocks
    pcen_kernel<<<grid, RPB>>>(x, out, ngroups);
}